// round 1
// baseline (speedup 1.0000x reference)
#include <cuda_runtime.h>
#include <math.h>

// Problem constants
#define EXPERTS 8
#define HID     2048
#define IEXP    1408      // per-expert intermediate
#define SIEXP   2816      // shared intermediate
#define TTOK    4096
#define NPAIR   8192      // TTOK * top_k

// Tile config
#define BM 64
#define BN 64
#define BK 16
#define ASTR 68           // padded A-smem row stride (16B aligned, low-conflict)

// ---------------- scratch (no allocations allowed) ----------------
__device__ int   g_cnt[EXPERTS];
__device__ int   g_tok[EXPERTS * NPAIR];
__device__ int   g_pid[EXPERTS * NPAIR];
__device__ float g_pw [EXPERTS * NPAIR];
// reused buffer: shared phase [TTOK][SIEXP] (=11,534,336) then routed phase [NPAIR][IEXP] (same size)
__device__ float g_act[11534336];
__device__ float g_pairout[NPAIR * HID];   // per (token,k) routed output rows

__device__ __forceinline__ float silu_f(float a) { return a / (1.0f + expf(-a)); }

// ---------------- routing ----------------
__global__ void zero_cnt_kernel() {
    if (threadIdx.x < EXPERTS) g_cnt[threadIdx.x] = 0;
}

__global__ void route_kernel(const int* __restrict__ topk_idx,
                             const float* __restrict__ topk_w) {
    int p = blockIdx.x * blockDim.x + threadIdx.x;
    if (p < NPAIR) {
        int e = topk_idx[p];
        int pos = atomicAdd(&g_cnt[e], 1);
        g_tok[e * NPAIR + pos] = p >> 1;       // token id
        g_pid[e * NPAIR + pos] = p;            // pair id (output row key -> determinism)
        g_pw [e * NPAIR + pos] = topk_w[p];
    }
}

// ---------------- shared expert GEMM1 (+ swiglu epilogue) ----------------
// g_act[t][0:SIEXP] = silu(x @ Ws1[:, :SI]) * (x @ Ws1[:, SI:])
__global__ __launch_bounds__(256) void sgemm1_kernel(const float* __restrict__ X,
                                                     const float* __restrict__ W) {
    __shared__ float As[BK][ASTR];
    __shared__ float Ba[BK][BN];
    __shared__ float Bb[BK][BN];
    const int tid = threadIdx.x;
    const int tx = tid & 15, ty = tid >> 4;
    const int n0 = blockIdx.x * BN;
    const int m0 = blockIdx.y * BM;
    const int ldw = 2 * SIEXP;

    float accA[4][4] = {{0.f}}, accB[4][4] = {{0.f}};

    for (int k0 = 0; k0 < HID; k0 += BK) {
        {   // A tile (64 rows x 16 k), transposed into As[k][m]
            int ar = tid >> 2, ac = (tid & 3) << 2;
            float4 av = *(const float4*)&X[(size_t)(m0 + ar) * HID + k0 + ac];
            As[ac + 0][ar] = av.x; As[ac + 1][ar] = av.y;
            As[ac + 2][ar] = av.z; As[ac + 3][ar] = av.w;
        }
        {   // B tiles for both swiglu halves
            int kr = tid >> 4, nc = (tid & 15) << 2;
            *(float4*)&Ba[kr][nc] = *(const float4*)&W[(size_t)(k0 + kr) * ldw + n0 + nc];
            *(float4*)&Bb[kr][nc] = *(const float4*)&W[(size_t)(k0 + kr) * ldw + SIEXP + n0 + nc];
        }
        __syncthreads();
        #pragma unroll
        for (int kk = 0; kk < BK; kk++) {
            float4 a  = *(float4*)&As[kk][ty << 2];
            float4 ba = *(float4*)&Ba[kk][tx << 2];
            float4 bb = *(float4*)&Bb[kk][tx << 2];
            float av[4]  = {a.x, a.y, a.z, a.w};
            float bav[4] = {ba.x, ba.y, ba.z, ba.w};
            float bbv[4] = {bb.x, bb.y, bb.z, bb.w};
            #pragma unroll
            for (int i = 0; i < 4; i++)
                #pragma unroll
                for (int j = 0; j < 4; j++) {
                    accA[i][j] += av[i] * bav[j];
                    accB[i][j] += av[i] * bbv[j];
                }
        }
        __syncthreads();
    }
    #pragma unroll
    for (int i = 0; i < 4; i++) {
        int row = m0 + (ty << 2) + i;
        #pragma unroll
        for (int j = 0; j < 4; j++) {
            int col = n0 + (tx << 2) + j;
            g_act[(size_t)row * SIEXP + col] = silu_f(accA[i][j]) * accB[i][j];
        }
    }
}

// ---------------- shared expert GEMM2 (writes out directly) ----------------
__global__ __launch_bounds__(256) void sgemm2_kernel(const float* __restrict__ W,
                                                     float* __restrict__ out) {
    __shared__ float As[BK][ASTR];
    __shared__ float Bs[BK][BN];
    const int tid = threadIdx.x;
    const int tx = tid & 15, ty = tid >> 4;
    const int n0 = blockIdx.x * BN;
    const int m0 = blockIdx.y * BM;

    float acc[4][4] = {{0.f}};

    for (int k0 = 0; k0 < SIEXP; k0 += BK) {
        {
            int ar = tid >> 2, ac = (tid & 3) << 2;
            float4 av = *(const float4*)&g_act[(size_t)(m0 + ar) * SIEXP + k0 + ac];
            As[ac + 0][ar] = av.x; As[ac + 1][ar] = av.y;
            As[ac + 2][ar] = av.z; As[ac + 3][ar] = av.w;
        }
        {
            int kr = tid >> 4, nc = (tid & 15) << 2;
            *(float4*)&Bs[kr][nc] = *(const float4*)&W[(size_t)(k0 + kr) * HID + n0 + nc];
        }
        __syncthreads();
        #pragma unroll
        for (int kk = 0; kk < BK; kk++) {
            float4 a = *(float4*)&As[kk][ty << 2];
            float4 b = *(float4*)&Bs[kk][tx << 2];
            float av[4] = {a.x, a.y, a.z, a.w};
            float bv[4] = {b.x, b.y, b.z, b.w};
            #pragma unroll
            for (int i = 0; i < 4; i++)
                #pragma unroll
                for (int j = 0; j < 4; j++) acc[i][j] += av[i] * bv[j];
        }
        __syncthreads();
    }
    #pragma unroll
    for (int i = 0; i < 4; i++) {
        int row = m0 + (ty << 2) + i;
        #pragma unroll
        for (int j = 0; j < 4; j++)
            out[(size_t)row * HID + n0 + (tx << 2) + j] = acc[i][j];
    }
}

// ---------------- routed GEMM1 (gather tokens, swiglu, scatter act by pair id) ----------------
__global__ __launch_bounds__(256) void rgemm1_kernel(const float* __restrict__ X,
                                                     const float* __restrict__ W1) {
    const int e = blockIdx.z;
    const int cnt = g_cnt[e];
    const int m0 = blockIdx.y * BM;
    if (m0 >= cnt) return;

    __shared__ float As[BK][ASTR];
    __shared__ float Ba[BK][BN];
    __shared__ float Bb[BK][BN];
    __shared__ int toks[BM];
    __shared__ int pids[BM];

    const int tid = threadIdx.x;
    const int tx = tid & 15, ty = tid >> 4;
    const int n0 = blockIdx.x * BN;
    const int ldw = 2 * IEXP;
    const float* W = W1 + (size_t)e * HID * (2 * IEXP);

    if (tid < BM) {
        int r = m0 + tid;
        bool ok = (r < cnt);
        toks[tid] = ok ? g_tok[e * NPAIR + r] : 0;
        pids[tid] = ok ? g_pid[e * NPAIR + r] : -1;
    }
    __syncthreads();

    float accA[4][4] = {{0.f}}, accB[4][4] = {{0.f}};

    for (int k0 = 0; k0 < HID; k0 += BK) {
        {
            int ar = tid >> 2, ac = (tid & 3) << 2;
            float4 av = *(const float4*)&X[(size_t)toks[ar] * HID + k0 + ac];
            As[ac + 0][ar] = av.x; As[ac + 1][ar] = av.y;
            As[ac + 2][ar] = av.z; As[ac + 3][ar] = av.w;
        }
        {
            int kr = tid >> 4, nc = (tid & 15) << 2;
            *(float4*)&Ba[kr][nc] = *(const float4*)&W[(size_t)(k0 + kr) * ldw + n0 + nc];
            *(float4*)&Bb[kr][nc] = *(const float4*)&W[(size_t)(k0 + kr) * ldw + IEXP + n0 + nc];
        }
        __syncthreads();
        #pragma unroll
        for (int kk = 0; kk < BK; kk++) {
            float4 a  = *(float4*)&As[kk][ty << 2];
            float4 ba = *(float4*)&Ba[kk][tx << 2];
            float4 bb = *(float4*)&Bb[kk][tx << 2];
            float av[4]  = {a.x, a.y, a.z, a.w};
            float bav[4] = {ba.x, ba.y, ba.z, ba.w};
            float bbv[4] = {bb.x, bb.y, bb.z, bb.w};
            #pragma unroll
            for (int i = 0; i < 4; i++)
                #pragma unroll
                for (int j = 0; j < 4; j++) {
                    accA[i][j] += av[i] * bav[j];
                    accB[i][j] += av[i] * bbv[j];
                }
        }
        __syncthreads();
    }
    #pragma unroll
    for (int i = 0; i < 4; i++) {
        int lm = (ty << 2) + i;
        int pid = pids[lm];
        if (pid >= 0) {
            #pragma unroll
            for (int j = 0; j < 4; j++) {
                int col = n0 + (tx << 2) + j;
                g_act[(size_t)pid * IEXP + col] = silu_f(accA[i][j]) * accB[i][j];
            }
        }
    }
}

// ---------------- routed GEMM2 (act @ W2[e], scaled by gate weight, to pairout) ----------------
__global__ __launch_bounds__(256) void rgemm2_kernel(const float* __restrict__ W2) {
    const int e = blockIdx.z;
    const int cnt = g_cnt[e];
    const int m0 = blockIdx.y * BM;
    if (m0 >= cnt) return;

    __shared__ float As[BK][ASTR];
    __shared__ float Bs[BK][BN];
    __shared__ int   pids[BM];
    __shared__ float ws[BM];

    const int tid = threadIdx.x;
    const int tx = tid & 15, ty = tid >> 4;
    const int n0 = blockIdx.x * BN;
    const float* W = W2 + (size_t)e * IEXP * HID;

    if (tid < BM) {
        int r = m0 + tid;
        bool ok = (r < cnt);
        pids[tid] = ok ? g_pid[e * NPAIR + r] : -1;
        ws[tid]   = ok ? g_pw [e * NPAIR + r] : 0.f;
    }
    __syncthreads();

    float acc[4][4] = {{0.f}};

    for (int k0 = 0; k0 < IEXP; k0 += BK) {
        {
            int ar = tid >> 2, ac = (tid & 3) << 2;
            int src = pids[ar] >= 0 ? pids[ar] : 0;
            float4 av = *(const float4*)&g_act[(size_t)src * IEXP + k0 + ac];
            As[ac + 0][ar] = av.x; As[ac + 1][ar] = av.y;
            As[ac + 2][ar] = av.z; As[ac + 3][ar] = av.w;
        }
        {
            int kr = tid >> 4, nc = (tid & 15) << 2;
            *(float4*)&Bs[kr][nc] = *(const float4*)&W[(size_t)(k0 + kr) * HID + n0 + nc];
        }
        __syncthreads();
        #pragma unroll
        for (int kk = 0; kk < BK; kk++) {
            float4 a = *(float4*)&As[kk][ty << 2];
            float4 b = *(float4*)&Bs[kk][tx << 2];
            float av[4] = {a.x, a.y, a.z, a.w};
            float bv[4] = {b.x, b.y, b.z, b.w};
            #pragma unroll
            for (int i = 0; i < 4; i++)
                #pragma unroll
                for (int j = 0; j < 4; j++) acc[i][j] += av[i] * bv[j];
        }
        __syncthreads();
    }
    #pragma unroll
    for (int i = 0; i < 4; i++) {
        int lm = (ty << 2) + i;
        int pid = pids[lm];
        if (pid >= 0) {
            float w = ws[lm];
            #pragma unroll
            for (int j = 0; j < 4; j++)
                g_pairout[(size_t)pid * HID + n0 + (tx << 2) + j] = w * acc[i][j];
        }
    }
}

// ---------------- combine: out(t) = shared(t) + pairout(2t) + pairout(2t+1) ----------------
__global__ void combine_kernel(float* __restrict__ out) {
    int v = blockIdx.x * blockDim.x + threadIdx.x;     // float4 index
    const int HV = HID / 4;
    if (v < TTOK * HV) {
        int t = v / HV;
        int h4 = v - t * HV;
        float4 o  = ((float4*)out)[v];
        float4 p0 = ((const float4*)g_pairout)[(size_t)(2 * t) * HV + h4];
        float4 p1 = ((const float4*)g_pairout)[(size_t)(2 * t + 1) * HV + h4];
        o.x += p0.x + p1.x; o.y += p0.y + p1.y;
        o.z += p0.z + p1.z; o.w += p0.w + p1.w;
        ((float4*)out)[v] = o;
    }
}

// ---------------- launcher ----------------
extern "C" void kernel_launch(void* const* d_in, const int* in_sizes, int n_in,
                              void* d_out, int out_size) {
    const float* x        = (const float*)d_in[0];  // [T, H]
    const float* topk_w   = (const float*)d_in[1];  // [T, 2]
    const float* W1       = (const float*)d_in[2];  // [E, H, 2I]
    const float* W2       = (const float*)d_in[3];  // [E, I, H]
    const float* Ws1      = (const float*)d_in[4];  // [H, 2SI]
    const float* Ws2      = (const float*)d_in[5];  // [SI, H]
    const int*   topk_idx = (const int*)d_in[6];    // [T, 2]
    float* out = (float*)d_out;                     // [T, H]

    (void)in_sizes; (void)n_in; (void)out_size;

    // routing
    zero_cnt_kernel<<<1, 32>>>();
    route_kernel<<<NPAIR / 256, 256>>>(topk_idx, topk_w);

    // shared expert path (writes out with plain stores)
    sgemm1_kernel<<<dim3(SIEXP / BN, TTOK / BM), 256>>>(x, Ws1);
    sgemm2_kernel<<<dim3(HID / BN, TTOK / BM), 256>>>(Ws2, out);

    // routed expert path (g_act reused after sgemm2 has consumed it)
    rgemm1_kernel<<<dim3(IEXP / BN, NPAIR / BM, EXPERTS), 256>>>(x, W1);
    rgemm2_kernel<<<dim3(HID / BN, NPAIR / BM, EXPERTS), 256>>>(W2);

    // deterministic combine
    combine_kernel<<<(TTOK * (HID / 4) + 255) / 256, 256>>>(out);
}